// round 1
// baseline (speedup 1.0000x reference)
#include <cuda_runtime.h>
#include <math.h>
#include <stdint.h>

#define HW   64
#define NPIX 4096   // 64*64

// Global scratch (allowed: __device__ globals, no allocation)
__device__ float g_bb[4][NPIX];   // pred bars: births, sorted by persistence desc
__device__ float g_bd[4][NPIX];   // pred bars: deaths
__device__ int   g_k1[4];         // pred positive-bar count
__device__ int   g_k2[4];         // tgt  positive-bar count

// Map float to uint32 with same total order (ascending)
__device__ __forceinline__ unsigned int ford(float f) {
    unsigned int u = __float_as_uint(f);
    return (u & 0x80000000u) ? ~u : (u | 0x80000000u);
}

// Shared memory layout (dynamic):
//   uint64 key[NPIX]        : 32768 B   (sort keys; reused for bar sort)
//   float  val[NPIX]        : 16384 B
//   int    par[NPIX]        : 16384 B
//   uchar  added[NPIX]      :  4096 B
//   float  barB[NPIX]       : 16384 B
//   float  barD[NPIX]       : 16384 B
//   int    cnt[4]           :    16 B
#define SMEM_BYTES (NPIX*8 + NPIX*4 + NPIX*4 + NPIX + NPIX*4 + NPIX*4 + 16)

extern __shared__ unsigned char smem_raw[];

__device__ __forceinline__ void bitonic_sort_4096(unsigned long long* key, int tid, int nthr) {
    for (int k = 2; k <= NPIX; k <<= 1) {
        for (int j = k >> 1; j > 0; j >>= 1) {
            for (int i = tid; i < NPIX; i += nthr) {
                int l = i ^ j;
                if (l > i) {
                    bool up = ((i & k) == 0);
                    unsigned long long a = key[i], b = key[l];
                    if ((a > b) == up) { key[i] = b; key[l] = a; }
                }
            }
            __syncthreads();
        }
    }
}

__global__ void __launch_bounds__(1024)
diagram_kernel(const float* __restrict__ input, const float* __restrict__ target)
{
    const int s    = blockIdx.x & 3;    // sample
    const int kind = blockIdx.x >> 2;   // 0 = pred, 1 = tgt
    const int tid  = threadIdx.x;
    const int nthr = blockDim.x;

    unsigned long long* key = (unsigned long long*)smem_raw;
    float* val   = (float*)(smem_raw + NPIX*8);
    int*   par   = (int*)  (smem_raw + NPIX*8 + NPIX*4);
    unsigned char* added = (unsigned char*)(smem_raw + NPIX*8 + NPIX*8);
    float* barB  = (float*)(smem_raw + NPIX*8 + NPIX*8 + NPIX);
    float* barD  = barB + NPIX;
    int*   cnt   = (int*)(barD + NPIX);

    // ---- fill values ----
    for (int i = tid; i < NPIX; i += nthr) {
        float v;
        if (kind == 0) {
            float l0 = input[(s*2 + 0)*NPIX + i];
            float l1 = input[(s*2 + 1)*NPIX + i];
            float m  = fmaxf(l0, l1);
            float e0 = expf(l0 - m), e1 = expf(l1 - m);
            v = e1 / (e0 + e1);              // softmax foreground channel
        } else {
            v = target[s*NPIX + i];
        }
        val[i]   = v;
        // sort key: value descending, index ascending (matches stable argsort(-vals))
        key[i]   = ((unsigned long long)(~ford(v)) << 32) | (unsigned int)i;
        par[i]   = i;
        added[i] = 0;
    }
    if (tid == 0) cnt[0] = 0;
    __syncthreads();

    // ---- sort pixels by value descending ----
    bitonic_sort_4096(key, tid, nthr);

    // ---- sequential union-find (thread 0), path-halving compression ----
    if (tid == 0) {
        int nb = 0;
        for (int t = 0; t < NPIX; ++t) {
            int   i  = (int)(key[t] & 0xFFFFFFFFu);
            added[i] = 1;
            float vi = val[i];
            int r = i >> 6, c = i & 63;
            int nbr0 = (r > 0)      ? i - HW : -1;
            int nbr1 = (r < HW - 1) ? i + HW : -1;
            int nbr2 = (c > 0)      ? i - 1  : -1;
            int nbr3 = (c < HW - 1) ? i + 1  : -1;
            int nbrs[4] = {nbr0, nbr1, nbr2, nbr3};
            #pragma unroll
            for (int kk = 0; kk < 4; ++kk) {
                int j = nbrs[kk];
                if (j < 0 || !added[j]) continue;
                int ri = i; while (par[ri] != ri) { par[ri] = par[par[ri]]; ri = par[ri]; }
                int rj = j; while (par[rj] != rj) { par[rj] = par[par[rj]]; rj = par[rj]; }
                if (ri == rj) continue;
                int young, elder;
                if (val[ri] >= val[rj]) { elder = ri; young = rj; }   // tie: current root is elder (ref)
                else                    { elder = rj; young = ri; }
                float pb = val[young];
                if (pb > vi) { barB[nb] = pb; barD[nb] = vi; ++nb; }  // only positive-persistence bars
                par[young] = elder;
            }
        }
        cnt[0] = nb;
    }
    __syncthreads();

    // ---- essential bars: surviving roots die at global min ----
    const float minv = val[(int)(key[NPIX - 1] & 0xFFFFFFFFu)];
    for (int i = tid; i < NPIX; i += nthr) {
        if (par[i] == i && val[i] > minv) {
            int slot = atomicAdd(cnt, 1);
            barB[slot] = val[i];
            barD[slot] = minv;
        }
    }
    __syncthreads();
    const int nb = cnt[0];

    if (kind == 1) {
        // target: all positive bars are exactly (1,0); only the count matters
        if (tid == 0) g_k2[s] = nb;
        return;
    }

    // ---- sort pred bars by persistence descending ----
    for (int i = tid; i < NPIX; i += nthr) {
        if (i < nb) {
            float p = barB[i] - barD[i];   // > 0 by construction
            key[i] = ((unsigned long long)(~ford(p)) << 32) | (unsigned int)i;
        } else {
            key[i] = 0xFFFFFFFFFFFFFFFFull;  // pad sinks to the end
        }
    }
    __syncthreads();
    bitonic_sort_4096(key, tid, nthr);

    for (int i = tid; i < nb; i += nthr) {
        int idx = (int)(key[i] & 0xFFFFFFFFu);
        g_bb[s][i] = barB[idx];
        g_bd[s][i] = barD[idx];
    }
    if (tid == 0) g_k1[s] = nb;
}

__global__ void __launch_bounds__(256)
loss_kernel(float* __restrict__ out)
{
    __shared__ float red[256];
    const int tid = threadIdx.x;
    float acc = 0.f;
    for (int s = 0; s < 4; ++s) {
        const int K1 = g_k1[s], K2 = g_k2[s];
        const int m  = min(K1, K2);
        for (int t = tid; t < K1; t += blockDim.x) {
            float b = g_bb[s][t], d = g_bd[s][t];
            if (t < m) {
                float db = b - 1.0f;
                acc += db * db + d * d;          // matched vs tgt bar (1,0)
            } else {
                float q = b - d;
                acc += 0.5f * q * q;             // unmatched pred bar
            }
        }
        if (tid == 0 && K2 > K1)
            acc += 0.5f * (float)(K2 - K1);      // unmatched tgt bars: 0.5*(1-0)^2 each
    }
    red[tid] = acc;
    __syncthreads();
    for (int off = 128; off > 0; off >>= 1) {
        if (tid < off) red[tid] += red[tid + off];
        __syncthreads();
    }
    if (tid == 0) out[0] = red[0] * 0.25f;       // mean over 4 samples
}

extern "C" void kernel_launch(void* const* d_in, const int* in_sizes, int n_in,
                              void* d_out, int out_size)
{
    (void)in_sizes; (void)n_in; (void)out_size;
    const float* input  = (const float*)d_in[0];   // (4,2,64,64) float32
    const float* target = (const float*)d_in[1];   // (4,64,64)   float32

    cudaFuncSetAttribute(diagram_kernel,
                         cudaFuncAttributeMaxDynamicSharedMemorySize, SMEM_BYTES);
    diagram_kernel<<<8, 1024, SMEM_BYTES>>>(input, target);
    loss_kernel<<<1, 256>>>((float*)d_out);
}

// round 2
// speedup vs baseline: 2.3380x; 2.3380x over previous
#include <cuda_runtime.h>
#include <math.h>
#include <stdint.h>

#define HW    64
#define NPIX  4096
#define NEDGE 8064      // 4032 horizontal + 4032 vertical
#define NTHR  1024

__device__ float g_bb[4][NPIX];
__device__ float g_bd[4][NPIX];
__device__ int   g_k1[4];
__device__ int   g_k2[4];

// monotone float<->uint order map
__device__ __forceinline__ unsigned ford(float f) {
    unsigned u = __float_as_uint(f);
    return (u & 0x80000000u) ? ~u : (u | 0x80000000u);
}
__device__ __forceinline__ float iford(unsigned m) {
    unsigned u = (m & 0x80000000u) ? (m ^ 0x80000000u) : ~m;
    return __uint_as_float(u);
}

// Shared layout (dynamic):
//   val  f32[4096]  @0        16384
//   par  i32[4096]  @16384    16384
//   best u64[4096]  @32768    32768
//   mkey u64[4096]  @65536    32768   (MST edge keys; reused for persistence sort)
//   barB f32[4096]  @98304    16384   (aliased as int tmp[] during Boruvka hook)
//   barD f32[4096]  @114688   16384
//   used u32[252]   @131072    1008
//   ctrl i32[4]     @132096      16   [0]=mstCnt [1]=chg [2]=minbits [3]=nbars
#define SMEM_BYTES (132096 + 64)

extern __shared__ unsigned char smem_raw[];

__device__ __forceinline__ void bitonic_sort_4096(unsigned long long* key, int tid) {
    for (int k = 2; k <= NPIX; k <<= 1) {
        for (int j = k >> 1; j > 0; j >>= 1) {
            #pragma unroll
            for (int rep = 0; rep < NPIX / NTHR; ++rep) {
                int i = tid + rep * NTHR;
                int l = i ^ j;
                if (l > i) {
                    bool up = ((i & k) == 0);
                    unsigned long long a = key[i], b = key[l];
                    if ((a > b) == up) { key[i] = b; key[l] = a; }
                }
            }
            __syncthreads();
        }
    }
}

__device__ __forceinline__ void edge_decode(int e, int& u, int& v) {
    if (e < 4032) { int r = e / 63, c = e - r * 63; u = r * 64 + c; v = u + 1; }
    else          { u = e - 4032; v = u + 64; }
}

__global__ void __launch_bounds__(1024)
diagram_kernel(const float* __restrict__ input, const float* __restrict__ target)
{
    const int s    = blockIdx.x & 3;
    const int kind = blockIdx.x >> 2;
    const int tid  = threadIdx.x;

    float* val = (float*)smem_raw;
    int*   par = (int*)(smem_raw + 16384);
    unsigned long long* best = (unsigned long long*)(smem_raw + 32768);
    unsigned long long* mkey = (unsigned long long*)(smem_raw + 65536);
    float* barB = (float*)(smem_raw + 98304);
    int*   tmp  = (int*)  (smem_raw + 98304);   // alias: only used during Boruvka
    float* barD = (float*)(smem_raw + 114688);
    unsigned* used = (unsigned*)(smem_raw + 131072);
    int* ctrl = (int*)(smem_raw + 132096);
    unsigned* uctrl = (unsigned*)ctrl;

    // hk(i): strict total order key; higher value => larger key; tie: smaller index higher
    #define HK(i) ((((unsigned long long)ford(val[(i)])) << 12) | (unsigned)(4095 - (i)))

    // ---- fill ----
    if (tid == 0) { ctrl[0] = 0; ctrl[3] = 0; uctrl[2] = 0xFFFFFFFFu; }
    for (int i = tid; i < 252; i += NTHR) used[i] = 0u;
    __syncthreads();
    #pragma unroll
    for (int rep = 0; rep < NPIX / NTHR; ++rep) {
        int i = tid + rep * NTHR;
        float v;
        if (kind == 0) {
            float l0 = input[(s * 2 + 0) * NPIX + i];
            float l1 = input[(s * 2 + 1) * NPIX + i];
            float m  = fmaxf(l0, l1);
            float e0 = expf(l0 - m), e1 = expf(l1 - m);
            v = e1 / (e0 + e1);
        } else {
            v = target[s * NPIX + i];
        }
        val[i] = v;
        par[i] = i;
        mkey[i] = ~0ull;
        atomicMin(&uctrl[2], ford(v));
    }
    __syncthreads();

    // ---- Boruvka max-spanning-forest; edge score = (min endpoint hk, edgeId) ----
    for (int round = 0; round < 13; ++round) {
        if (ctrl[0] >= NPIX - 1) break;
        __syncthreads();
        #pragma unroll
        for (int rep = 0; rep < NPIX / NTHR; ++rep) best[tid + rep * NTHR] = 0ull;
        __syncthreads();

        // edge pass: each component collects its max-score outgoing edge
        for (int e = tid; e < NEDGE; e += NTHR) {
            int u, v; edge_decode(e, u, v);
            int ru = par[u], rv = par[v];       // par is flattened
            if (ru == rv) continue;
            unsigned long long hu = HK(u), hv = HK(v);
            unsigned long long low = hu < hv ? hu : hv;
            unsigned long long sc = (low << 13) | (unsigned)e;
            atomicMax(&best[ru], sc);
            atomicMax(&best[rv], sc);
        }
        __syncthreads();

        // phase1: compute hook targets on frozen par; record MST edges (deduped)
        #pragma unroll
        for (int rep = 0; rep < NPIX / NTHR; ++rep) {
            int r = tid + rep * NTHR;
            if (par[r] == r) {
                unsigned long long sc = best[r];
                if (sc) {
                    int e = (int)(sc & 0x1FFF);
                    int u, v; edge_decode(e, u, v);
                    int ru = par[u], rv = par[v];
                    tmp[r] = (ru == r) ? rv : ru;
                    int w = e >> 5; unsigned b = 1u << (e & 31);
                    if (!(atomicOr(&used[w], b) & b)) {
                        int slot = atomicAdd(&ctrl[0], 1);
                        if (slot < NPIX) mkey[slot] = ~sc;
                    }
                }
            }
        }
        __syncthreads();

        // phase2: hook
        #pragma unroll
        for (int rep = 0; rep < NPIX / NTHR; ++rep) {
            int r = tid + rep * NTHR;
            if (par[r] == r && best[r]) par[r] = tmp[r];
        }
        __syncthreads();

        // phase3: break mutual 2-cycles (keep smaller index as root)
        #pragma unroll
        for (int rep = 0; rep < NPIX / NTHR; ++rep) {
            int r = tid + rep * NTHR;
            int p = par[r];
            if (p != r && par[p] == r && r < p) par[r] = r;
        }
        __syncthreads();

        // flatten (pointer jumping)
        for (;;) {
            if (tid == 0) ctrl[1] = 0;
            __syncthreads();
            int c = 0;
            #pragma unroll
            for (int rep = 0; rep < NPIX / NTHR; ++rep) {
                int i = tid + rep * NTHR;
                int p = par[i]; int pp = par[p];
                if (p != pp) { par[i] = pp; c = 1; }
            }
            if (c) ctrl[1] = 1;
            __syncthreads();
            if (!ctrl[1]) break;
        }
        __syncthreads();
    }
    __syncthreads();
    const int nmst = ctrl[0];

    // ---- sort MST edges: ~score ascending == Kruskal order (higher edges first) ----
    bitonic_sort_4096(mkey, tid);

    // reset UF for pairing
    #pragma unroll
    for (int rep = 0; rep < NPIX / NTHR; ++rep) { int i = tid + rep * NTHR; par[i] = i; }
    __syncthreads();

    // ---- serial Kruskal pairing over MST edges (thread 0) ----
    if (tid == 0) {
        int nb = 0;
        for (int t = 0; t < nmst; ++t) {
            unsigned long long sc = ~mkey[t];
            int e = (int)(sc & 0x1FFF);
            int u, v; edge_decode(e, u, v);
            int ru = u; for (;;) { int p = par[ru]; if (p == ru) break; int gp = par[p]; par[ru] = gp; ru = gp; }
            int rv = v; for (;;) { int p = par[rv]; if (p == rv) break; int gp = par[p]; par[rv] = gp; rv = gp; }
            unsigned long long hu = HK(ru), hv = HK(rv);
            int elder, young;
            if (hu > hv) { elder = ru; young = rv; } else { elder = rv; young = ru; }
            int dIdx = 4095 - (int)((sc >> 13) & 0xFFF);   // lower endpoint = death pixel
            float dv = val[dIdx];
            float bv = val[young];
            if (bv > dv) { barB[nb] = bv; barD[nb] = dv; ++nb; }
            par[young] = elder;
        }
        ctrl[3] = nb;
    }
    __syncthreads();

    // ---- essential bars: surviving roots die at global min ----
    const float minv = iford(uctrl[2]);
    #pragma unroll
    for (int rep = 0; rep < NPIX / NTHR; ++rep) {
        int i = tid + rep * NTHR;
        if (par[i] == i && val[i] > minv) {
            int slot = atomicAdd(&ctrl[3], 1);
            barB[slot] = val[i];
            barD[slot] = minv;
        }
    }
    __syncthreads();
    const int nb = ctrl[3];

    if (kind == 1) {
        if (tid == 0) g_k2[s] = nb;
        return;
    }

    // ---- sort pred bars by persistence descending (reuse mkey) ----
    #pragma unroll
    for (int rep = 0; rep < NPIX / NTHR; ++rep) {
        int i = tid + rep * NTHR;
        if (i < nb) {
            float p = barB[i] - barD[i];
            mkey[i] = (((unsigned long long)(~ford(p))) << 32) | (unsigned)i;
        } else {
            mkey[i] = ~0ull;
        }
    }
    __syncthreads();
    bitonic_sort_4096(mkey, tid);

    for (int i = tid; i < nb; i += NTHR) {
        int idx = (int)(mkey[i] & 0xFFFFFFFFu);
        g_bb[s][i] = barB[idx];
        g_bd[s][i] = barD[idx];
    }
    if (tid == 0) g_k1[s] = nb;
    #undef HK
}

__global__ void __launch_bounds__(256)
loss_kernel(float* __restrict__ out)
{
    __shared__ float red[256];
    const int tid = threadIdx.x;
    float acc = 0.f;
    for (int s = 0; s < 4; ++s) {
        const int K1 = g_k1[s], K2 = g_k2[s];
        const int m  = min(K1, K2);
        for (int t = tid; t < K1; t += blockDim.x) {
            float b = g_bb[s][t], d = g_bd[s][t];
            if (t < m) {
                float db = b - 1.0f;
                acc += db * db + d * d;
            } else {
                float q = b - d;
                acc += 0.5f * q * q;
            }
        }
        if (tid == 0 && K2 > K1)
            acc += 0.5f * (float)(K2 - K1);
    }
    red[tid] = acc;
    __syncthreads();
    for (int off = 128; off > 0; off >>= 1) {
        if (tid < off) red[tid] += red[tid + off];
        __syncthreads();
    }
    if (tid == 0) out[0] = red[0] * 0.25f;
}

extern "C" void kernel_launch(void* const* d_in, const int* in_sizes, int n_in,
                              void* d_out, int out_size)
{
    (void)in_sizes; (void)n_in; (void)out_size;
    const float* input  = (const float*)d_in[0];   // (4,2,64,64) float32
    const float* target = (const float*)d_in[1];   // (4,64,64)   float32

    cudaFuncSetAttribute(diagram_kernel,
                         cudaFuncAttributeMaxDynamicSharedMemorySize, SMEM_BYTES);
    diagram_kernel<<<8, NTHR, SMEM_BYTES>>>(input, target);
    loss_kernel<<<1, 256>>>((float*)d_out);
}

// round 3
// speedup vs baseline: 9.4532x; 4.0434x over previous
#include <cuda_runtime.h>
#include <math.h>
#include <stdint.h>

#define HW    64
#define NPIX  4096
#define NEDGE 8064      // 4032 horizontal + 4032 vertical
#define NTHR  1024

__device__ float g_bb[4][NPIX];
__device__ float g_bd[4][NPIX];
__device__ int   g_k1[4];
__device__ int   g_k2[4];

// monotone float<->uint order map
__device__ __forceinline__ unsigned ford(float f) {
    unsigned u = __float_as_uint(f);
    return (u & 0x80000000u) ? ~u : (u | 0x80000000u);
}
__device__ __forceinline__ float iford(unsigned m) {
    unsigned u = (m & 0x80000000u) ? (m ^ 0x80000000u) : ~m;
    return __uint_as_float(u);
}

// Shared layout (dynamic):
//   val  f32[4096]  @0        16384
//   par  i32[4096]  @16384    16384
//   best u64[4096]  @32768    32768
//   mkey u64[4096]  @65536    32768   (MST edge keys; reused for persistence sort)
//   barB f32[4096]  @98304    16384   (aliased as int tmp[] during Boruvka hook)
//   barD f32[4096]  @114688   16384
//   used u32[252]   @131072    1008
//   ctrl i32[8]     @132096      32   [0]=mstCnt [1]=chg/act [2]=minbits [3]=nbars
//   hk64 u64[4096]  @132160   32768
//   peak i32[4096]  @164928   16384   -> total 181312
#define SMEM_BYTES 181312

extern __shared__ unsigned char smem_raw[];

__device__ __forceinline__ void bitonic_sort(unsigned long long* key, int P, int tid) {
    for (int k = 2; k <= P; k <<= 1) {
        for (int j = k >> 1; j > 0; j >>= 1) {
            for (int i = tid; i < P; i += NTHR) {
                int l = i ^ j;
                if (l > i) {
                    bool up = ((i & k) == 0);
                    unsigned long long a = key[i], b = key[l];
                    if ((a > b) == up) { key[i] = b; key[l] = a; }
                }
            }
            __syncthreads();
        }
    }
}

__device__ __forceinline__ void edge_decode(int e, int& u, int& v) {
    if (e < 4032) { int r = e / 63, c = e - r * 63; u = r * 64 + c; v = u + 1; }
    else          { u = e - 4032; v = u + 64; }
}

__global__ void __launch_bounds__(1024)
diagram_kernel(const float* __restrict__ input, const float* __restrict__ target)
{
    const int s    = blockIdx.x & 3;
    const int kind = blockIdx.x >> 2;
    const int tid  = threadIdx.x;

    float* val = (float*)smem_raw;
    int*   par = (int*)(smem_raw + 16384);
    unsigned long long* best = (unsigned long long*)(smem_raw + 32768);
    unsigned long long* mkey = (unsigned long long*)(smem_raw + 65536);
    float* barB = (float*)(smem_raw + 98304);
    int*   tmp  = (int*)  (smem_raw + 98304);   // alias: only used during Boruvka
    float* barD = (float*)(smem_raw + 114688);
    unsigned* used = (unsigned*)(smem_raw + 131072);
    int* ctrl = (int*)(smem_raw + 132096);
    unsigned* uctrl = (unsigned*)ctrl;
    unsigned long long* hk = (unsigned long long*)(smem_raw + 132160);
    int* peak = (int*)(smem_raw + 164928);

    // ---- fill ----
    if (tid == 0) { ctrl[0] = 0; ctrl[3] = 0; uctrl[2] = 0xFFFFFFFFu; }
    for (int i = tid; i < 252; i += NTHR) used[i] = 0u;
    __syncthreads();
    #pragma unroll
    for (int rep = 0; rep < NPIX / NTHR; ++rep) {
        int i = tid + rep * NTHR;
        float v;
        if (kind == 0) {
            float l0 = input[(s * 2 + 0) * NPIX + i];
            float l1 = input[(s * 2 + 1) * NPIX + i];
            float m  = fmaxf(l0, l1);
            float e0 = expf(l0 - m), e1 = expf(l1 - m);
            v = e1 / (e0 + e1);
        } else {
            v = target[s * NPIX + i];
        }
        val[i] = v;
        // strict total order key: higher value => larger; tie: smaller index larger
        hk[i] = (((unsigned long long)ford(v)) << 12) | (unsigned)(4095 - i);
        mkey[i] = ~0ull;
        atomicMin(&uctrl[2], ford(v));
    }
    __syncthreads();

    // ---- round-1 hook: each vertex's max-score incident edge (to a strictly
    //      higher neighbor). Edge-id priority among higher nbrs: down > up > right > left.
    //      These edges are MST edges and provably yield zero-persistence bars
    //      -> contract them (pointer-double to peak labels).
    #pragma unroll
    for (int rep = 0; rep < NPIX / NTHR; ++rep) {
        int i = tid + rep * NTHR;
        unsigned long long h = hk[i];
        int r = i >> 6, c = i & 63;
        int p = i;
        if      (r < HW - 1 && hk[i + HW] > h) p = i + HW;   // down edge id 4032+i
        else if (r > 0      && hk[i - HW] > h) p = i - HW;   // up   edge id 4032+i-64
        else if (c < HW - 1 && hk[i + 1]  > h) p = i + 1;    // right
        else if (c > 0      && hk[i - 1]  > h) p = i - 1;    // left
        par[i] = p;
    }
    __syncthreads();
    // pointer doubling (depth <= 4095 -> 12 rounds)
    for (int d = 0; d < 12; ++d) {
        #pragma unroll
        for (int rep = 0; rep < NPIX / NTHR; ++rep) {
            int i = tid + rep * NTHR;
            par[i] = par[par[i]];
        }
        __syncthreads();
    }
    #pragma unroll
    for (int rep = 0; rep < NPIX / NTHR; ++rep) {
        int i = tid + rep * NTHR;
        peak[i] = par[i];
    }
    __syncthreads();

    // ---- Boruvka max-spanning-forest over regions; edge score = (min endpoint hk, edgeId) ----
    for (int round = 0; round < 13; ++round) {
        if (tid == 0) ctrl[1] = 0;
        #pragma unroll
        for (int rep = 0; rep < NPIX / NTHR; ++rep) best[tid + rep * NTHR] = 0ull;
        __syncthreads();

        // edge pass: each component collects its max-score outgoing edge
        for (int e = tid; e < NEDGE; e += NTHR) {
            int u, v; edge_decode(e, u, v);
            int ru = par[u], rv = par[v];       // par is flattened
            if (ru == rv) continue;
            unsigned long long hu = hk[u], hv = hk[v];
            unsigned long long low = hu < hv ? hu : hv;
            unsigned long long sc = (low << 13) | (unsigned)e;
            atomicMax(&best[ru], sc);
            atomicMax(&best[rv], sc);
            ctrl[1] = 1;
        }
        __syncthreads();
        if (!ctrl[1]) break;
        __syncthreads();

        // phase1: compute hook targets on frozen par; record MST edges (deduped)
        #pragma unroll
        for (int rep = 0; rep < NPIX / NTHR; ++rep) {
            int r = tid + rep * NTHR;
            if (par[r] == r) {
                unsigned long long sc = best[r];
                if (sc) {
                    int e = (int)(sc & 0x1FFF);
                    int u, v; edge_decode(e, u, v);
                    int ru = par[u], rv = par[v];
                    tmp[r] = (ru == r) ? rv : ru;
                    int w = e >> 5; unsigned b = 1u << (e & 31);
                    if (!(atomicOr(&used[w], b) & b)) {
                        int slot = atomicAdd(&ctrl[0], 1);
                        if (slot < NPIX) mkey[slot] = ~sc;
                    }
                }
            }
        }
        __syncthreads();

        // phase2: hook
        #pragma unroll
        for (int rep = 0; rep < NPIX / NTHR; ++rep) {
            int r = tid + rep * NTHR;
            if (par[r] == r && best[r]) par[r] = tmp[r];
        }
        __syncthreads();

        // phase3: break mutual 2-cycles (keep smaller index as root)
        #pragma unroll
        for (int rep = 0; rep < NPIX / NTHR; ++rep) {
            int r = tid + rep * NTHR;
            int p = par[r];
            if (p != r && par[p] == r && r < p) par[r] = r;
        }
        __syncthreads();

        // flatten (pointer jumping)
        for (;;) {
            if (tid == 0) ctrl[4] = 0;
            __syncthreads();
            int chg = 0;
            #pragma unroll
            for (int rep = 0; rep < NPIX / NTHR; ++rep) {
                int i = tid + rep * NTHR;
                int p = par[i]; int pp = par[p];
                if (p != pp) { par[i] = pp; chg = 1; }
            }
            if (chg) ctrl[4] = 1;
            __syncthreads();
            if (!ctrl[4]) break;
        }
        __syncthreads();
    }
    __syncthreads();
    const int nmst = min(ctrl[0], NPIX);

    // ---- sort MST edges: ~score ascending == Kruskal order (higher edges first) ----
    const int P = (nmst <= 1024) ? 1024 : ((nmst <= 2048) ? 2048 : 4096);
    bitonic_sort(mkey, P, tid);

    // reset pairing UF: seed with contracted regions (peaks are roots)
    #pragma unroll
    for (int rep = 0; rep < NPIX / NTHR; ++rep) {
        int i = tid + rep * NTHR;
        par[i] = peak[i];
    }
    __syncthreads();

    // ---- serial Kruskal pairing over region-level MST edges (thread 0) ----
    if (tid == 0) {
        int nb = 0;
        for (int t = 0; t < nmst; ++t) {
            unsigned long long sc = ~mkey[t];
            int e = (int)(sc & 0x1FFF);
            int u, v; edge_decode(e, u, v);
            int ru = par[u]; for (;;) { int p = par[ru]; if (p == ru) break; int gp = par[p]; par[ru] = gp; ru = gp; }
            int rv = par[v]; for (;;) { int p = par[rv]; if (p == rv) break; int gp = par[p]; par[rv] = gp; rv = gp; }
            unsigned long long hu = hk[ru], hv = hk[rv];
            int elder, young;
            if (hu > hv) { elder = ru; young = rv; } else { elder = rv; young = ru; }
            int dIdx = 4095 - (int)((sc >> 13) & 0xFFF);   // lower endpoint = death pixel
            float dv = val[dIdx];
            float bv = val[young];
            if (bv > dv) { barB[nb] = bv; barD[nb] = dv; ++nb; }
            par[young] = elder;
        }
        ctrl[3] = nb;
    }
    __syncthreads();

    // ---- essential bars: surviving roots die at global min ----
    const float minv = iford(uctrl[2]);
    #pragma unroll
    for (int rep = 0; rep < NPIX / NTHR; ++rep) {
        int i = tid + rep * NTHR;
        if (par[i] == i && val[i] > minv) {
            int slot = atomicAdd(&ctrl[3], 1);
            barB[slot] = val[i];
            barD[slot] = minv;
        }
    }
    __syncthreads();
    const int nb = ctrl[3];

    if (kind == 1) {
        if (tid == 0) g_k2[s] = nb;
        return;
    }

    // ---- sort pred bars by persistence descending (reuse mkey) ----
    const int P2 = (nb <= 1024) ? 1024 : ((nb <= 2048) ? 2048 : 4096);
    for (int i = tid; i < P2; i += NTHR) {
        if (i < nb) {
            float p = barB[i] - barD[i];
            mkey[i] = (((unsigned long long)(~ford(p))) << 32) | (unsigned)i;
        } else {
            mkey[i] = ~0ull;
        }
    }
    __syncthreads();
    bitonic_sort(mkey, P2, tid);

    for (int i = tid; i < nb; i += NTHR) {
        int idx = (int)(mkey[i] & 0xFFFFFFFFu);
        g_bb[s][i] = barB[idx];
        g_bd[s][i] = barD[idx];
    }
    if (tid == 0) g_k1[s] = nb;
}

__global__ void __launch_bounds__(256)
loss_kernel(float* __restrict__ out)
{
    __shared__ float red[256];
    const int tid = threadIdx.x;
    float acc = 0.f;
    for (int s = 0; s < 4; ++s) {
        const int K1 = g_k1[s], K2 = g_k2[s];
        const int m  = min(K1, K2);
        for (int t = tid; t < K1; t += blockDim.x) {
            float b = g_bb[s][t], d = g_bd[s][t];
            if (t < m) {
                float db = b - 1.0f;
                acc += db * db + d * d;
            } else {
                float q = b - d;
                acc += 0.5f * q * q;
            }
        }
        if (tid == 0 && K2 > K1)
            acc += 0.5f * (float)(K2 - K1);
    }
    red[tid] = acc;
    __syncthreads();
    for (int off = 128; off > 0; off >>= 1) {
        if (tid < off) red[tid] += red[tid + off];
        __syncthreads();
    }
    if (tid == 0) out[0] = red[0] * 0.25f;
}

extern "C" void kernel_launch(void* const* d_in, const int* in_sizes, int n_in,
                              void* d_out, int out_size)
{
    (void)in_sizes; (void)n_in; (void)out_size;
    const float* input  = (const float*)d_in[0];   // (4,2,64,64) float32
    const float* target = (const float*)d_in[1];   // (4,64,64)   float32

    cudaFuncSetAttribute(diagram_kernel,
                         cudaFuncAttributeMaxDynamicSharedMemorySize, SMEM_BYTES);
    diagram_kernel<<<8, NTHR, SMEM_BYTES>>>(input, target);
    loss_kernel<<<1, 256>>>((float*)d_out);
}

// round 4
// speedup vs baseline: 12.2506x; 1.2959x over previous
#include <cuda_runtime.h>
#include <math.h>
#include <stdint.h>

#define HW    64
#define NPIX  4096
#define NEDGE 8064      // 4032 horizontal + 4032 vertical
#define NTHR  1024
#define FULLM 0xFFFFFFFFu

__device__ float g_bb[4][NPIX];
__device__ float g_bd[4][NPIX];
__device__ int   g_k1[4];
__device__ int   g_k2[4];
__device__ int   g_done;        // zero-initialized; finisher resets to 0

// monotone float<->uint order map
__device__ __forceinline__ unsigned ford(float f) {
    unsigned u = __float_as_uint(f);
    return (u & 0x80000000u) ? ~u : (u | 0x80000000u);
}
__device__ __forceinline__ float iford(unsigned m) {
    unsigned u = (m & 0x80000000u) ? (m ^ 0x80000000u) : ~m;
    return __uint_as_float(u);
}

// Shared layout (dynamic):
//   val  f32[4096]  @0        16384
//   par  i32[4096]  @16384    16384
//   best u64[4096]  @32768    32768   (reused as loss-reduction scratch)
//   mkey u64[4096]  @65536    32768   (MST edge keys; reused for persistence sort)
//   barB f32[4096]  @98304    16384   (aliased as int tmp[] during Boruvka hook)
//   barD f32[4096]  @114688   16384
//   used u32[252]   @131072    1008
//   ctrl i32[8]     @132096      32   [0]=mstCnt [1]=act [2]=minbits [3]=nbars [4]=chg [5]=finish
//   hk64 u64[4096]  @132160   32768
//   peak i32[4096]  @164928   16384   -> total 181312
#define SMEM_BYTES 181312

extern __shared__ unsigned char smem_raw[];

__device__ __forceinline__ void bitonic_sort(unsigned long long* key, int P, int tid) {
    for (int k = 2; k <= P; k <<= 1) {
        for (int j = k >> 1; j > 0; j >>= 1) {
            for (int i = tid; i < P; i += NTHR) {
                int l = i ^ j;
                if (l > i) {
                    bool up = ((i & k) == 0);
                    unsigned long long a = key[i], b = key[l];
                    if ((a > b) == up) { key[i] = b; key[l] = a; }
                }
            }
            __syncthreads();
        }
    }
}

__device__ __forceinline__ void edge_decode(int e, int& u, int& v) {
    if (e < 4032) { int r = e / 63, c = e - r * 63; u = r * 64 + c; v = u + 1; }
    else          { u = e - 4032; v = u + 64; }
}

__global__ void __launch_bounds__(1024)
diagram_kernel(const float* __restrict__ input, const float* __restrict__ target,
               float* __restrict__ out)
{
    const int s    = blockIdx.x & 3;
    const int kind = blockIdx.x >> 2;
    const int tid  = threadIdx.x;

    float* val = (float*)smem_raw;
    int*   par = (int*)(smem_raw + 16384);
    unsigned long long* best = (unsigned long long*)(smem_raw + 32768);
    unsigned long long* mkey = (unsigned long long*)(smem_raw + 65536);
    float* barB = (float*)(smem_raw + 98304);
    int*   tmp  = (int*)  (smem_raw + 98304);   // alias: only used during Boruvka
    float* barD = (float*)(smem_raw + 114688);
    unsigned* used = (unsigned*)(smem_raw + 131072);
    int* ctrl = (int*)(smem_raw + 132096);
    unsigned* uctrl = (unsigned*)ctrl;
    unsigned long long* hk = (unsigned long long*)(smem_raw + 132160);
    int* peak = (int*)(smem_raw + 164928);

    // ---- fill ----
    if (tid == 0) { ctrl[0] = 0; ctrl[3] = 0; uctrl[2] = 0xFFFFFFFFu; }
    for (int i = tid; i < 252; i += NTHR) used[i] = 0u;
    __syncthreads();
    #pragma unroll
    for (int rep = 0; rep < NPIX / NTHR; ++rep) {
        int i = tid + rep * NTHR;
        float v;
        if (kind == 0) {
            float l0 = input[(s * 2 + 0) * NPIX + i];
            float l1 = input[(s * 2 + 1) * NPIX + i];
            float m  = fmaxf(l0, l1);
            float e0 = expf(l0 - m), e1 = expf(l1 - m);
            v = e1 / (e0 + e1);
        } else {
            v = target[s * NPIX + i];
        }
        val[i] = v;
        // strict total order key: higher value => larger; tie: smaller index larger
        hk[i] = (((unsigned long long)ford(v)) << 12) | (unsigned)(4095 - i);
        mkey[i] = ~0ull;
        unsigned fb = ford(v);
        unsigned wmin = __reduce_min_sync(FULLM, fb);
        if ((tid & 31) == 0) atomicMin(&uctrl[2], wmin);
    }
    __syncthreads();

    // ---- round-1 hook: steepest strictly-higher neighbor (zero-persistence
    //      MST edges) -> contract to peak labels via pointer doubling ----
    #pragma unroll
    for (int rep = 0; rep < NPIX / NTHR; ++rep) {
        int i = tid + rep * NTHR;
        unsigned long long h = hk[i];
        int r = i >> 6, c = i & 63;
        int p = i;
        if      (r < HW - 1 && hk[i + HW] > h) p = i + HW;
        else if (r > 0      && hk[i - HW] > h) p = i - HW;
        else if (c < HW - 1 && hk[i + 1]  > h) p = i + 1;
        else if (c > 0      && hk[i - 1]  > h) p = i - 1;
        par[i] = p;
    }
    __syncthreads();
    for (int d = 0; d < 12; ++d) {
        #pragma unroll
        for (int rep = 0; rep < NPIX / NTHR; ++rep) {
            int i = tid + rep * NTHR;
            par[i] = par[par[i]];
        }
        __syncthreads();
    }
    #pragma unroll
    for (int rep = 0; rep < NPIX / NTHR; ++rep) {
        int i = tid + rep * NTHR;
        peak[i] = par[i];
    }
    __syncthreads();

    // ---- Boruvka max-spanning-forest over regions; score = (min endpoint hk, edgeId) ----
    for (int round = 0; round < 13; ++round) {
        if (tid == 0) ctrl[1] = 0;
        #pragma unroll
        for (int rep = 0; rep < NPIX / NTHR; ++rep) best[tid + rep * NTHR] = 0ull;
        __syncthreads();

        int any = 0;
        for (int e = tid; e < NEDGE; e += NTHR) {
            int u, v; edge_decode(e, u, v);
            int ru = par[u], rv = par[v];       // par is flattened
            if (ru == rv) continue;
            unsigned long long hu = hk[u], hv = hk[v];
            unsigned long long low = hu < hv ? hu : hv;
            unsigned long long sc = (low << 13) | (unsigned)e;
            atomicMax(&best[ru], sc);
            atomicMax(&best[rv], sc);
            any = 1;
        }
        if (any) ctrl[1] = 1;
        __syncthreads();
        if (!ctrl[1]) break;
        __syncthreads();

        // phase1: hook targets on frozen par; record MST edges (deduped)
        #pragma unroll
        for (int rep = 0; rep < NPIX / NTHR; ++rep) {
            int r = tid + rep * NTHR;
            if (par[r] == r) {
                unsigned long long sc = best[r];
                if (sc) {
                    int e = (int)(sc & 0x1FFF);
                    int u, v; edge_decode(e, u, v);
                    int ru = par[u], rv = par[v];
                    tmp[r] = (ru == r) ? rv : ru;
                    int w = e >> 5; unsigned b = 1u << (e & 31);
                    if (!(atomicOr(&used[w], b) & b)) {
                        int slot = atomicAdd(&ctrl[0], 1);
                        if (slot < NPIX) mkey[slot] = ~sc;
                    }
                }
            }
        }
        __syncthreads();

        // phase2: hook
        #pragma unroll
        for (int rep = 0; rep < NPIX / NTHR; ++rep) {
            int r = tid + rep * NTHR;
            if (par[r] == r && best[r]) par[r] = tmp[r];
        }
        __syncthreads();

        // phase3: break mutual 2-cycles (keep smaller index as root)
        #pragma unroll
        for (int rep = 0; rep < NPIX / NTHR; ++rep) {
            int r = tid + rep * NTHR;
            int p = par[r];
            if (p != r && par[p] == r && r < p) par[r] = r;
        }
        __syncthreads();

        // flatten (two jump passes per convergence check)
        for (;;) {
            if (tid == 0) ctrl[4] = 0;
            __syncthreads();
            int chg = 0;
            #pragma unroll
            for (int rep = 0; rep < NPIX / NTHR; ++rep) {
                int i = tid + rep * NTHR;
                par[i] = par[par[i]];
            }
            #pragma unroll
            for (int rep = 0; rep < NPIX / NTHR; ++rep) {
                int i = tid + rep * NTHR;
                int p = par[i]; int pp = par[p];
                if (p != pp) { par[i] = pp; chg = 1; }
            }
            if (chg) ctrl[4] = 1;
            __syncthreads();
            if (!ctrl[4]) break;
        }
        __syncthreads();
    }
    __syncthreads();
    const int nmst = min(ctrl[0], NPIX);

    // ---- sort MST edges: ~score ascending == Kruskal order (higher edges first) ----
    const int P = (nmst <= 1024) ? 1024 : ((nmst <= 2048) ? 2048 : 4096);
    bitonic_sort(mkey, P, tid);

    // reset pairing UF: seed with contracted regions (peaks are roots)
    #pragma unroll
    for (int rep = 0; rep < NPIX / NTHR; ++rep) {
        int i = tid + rep * NTHR;
        par[i] = peak[i];
    }
    __syncthreads();

    // ---- warp-speculative Kruskal pairing (warp 0) ----
    if (tid < 32) {
        for (int base = 0; base < nmst; base += 32) {
            int t = base + tid;
            bool has = t < nmst;
            int dIdx = 0, ru = 0, rv = 0;
            unsigned long long hu = 0, hv = 0;
            if (has) {
                unsigned long long sc = ~mkey[t];
                int e = (int)(sc & 0x1FFF);
                int uu, vv; edge_decode(e, uu, vv);
                dIdx = 4095 - (int)((sc >> 13) & 0xFFF);   // lower endpoint = death pixel
                ru = par[uu];
                for (;;) { int p = par[ru]; if (p == ru) break; int gp = par[p]; par[ru] = gp; ru = gp; }
                rv = par[vv];
                for (;;) { int p = par[rv]; if (p == rv) break; int gp = par[p]; par[rv] = gp; rv = gp; }
                hu = hk[ru]; hv = hk[rv];
            }
            __syncwarp(FULLM);
            // serialize merges in registers: lane k finalizes on its turn,
            // later lanes patch speculative roots via shuffles only.
            int young = -1, elder = -1;
            unsigned long long ehk = 0;
            #pragma unroll 4
            for (int k = 0; k < 32; ++k) {
                if (tid == k && has && ru != rv) {
                    if (hu > hv) { elder = ru; young = rv; ehk = hu; }
                    else         { elder = rv; young = ru; ehk = hv; }
                }
                int yk = __shfl_sync(FULLM, young, k);
                int ek = __shfl_sync(FULLM, elder, k);
                unsigned long long eh = __shfl_sync(FULLM, ehk, k);
                if (yk >= 0 && tid > k) {
                    if (ru == yk) { ru = ek; hu = eh; }
                    if (rv == yk) { rv = ek; hv = eh; }
                }
            }
            // apply merges + emit bars (parallel, distinct youngs)
            if (young >= 0) {
                par[young] = elder;
                float bv = val[young];
                float dv = val[dIdx];
                if (bv > dv) {
                    int slot = atomicAdd(&ctrl[3], 1);
                    barB[slot] = bv; barD[slot] = dv;
                }
            }
            __syncwarp(FULLM);
        }
    }
    __syncthreads();

    // ---- essential bars: surviving roots die at global min ----
    const float minv = iford(uctrl[2]);
    #pragma unroll
    for (int rep = 0; rep < NPIX / NTHR; ++rep) {
        int i = tid + rep * NTHR;
        if (par[i] == i && val[i] > minv) {
            int slot = atomicAdd(&ctrl[3], 1);
            barB[slot] = val[i];
            barD[slot] = minv;
        }
    }
    __syncthreads();
    const int nb = ctrl[3];

    if (kind == 1) {
        if (tid == 0) g_k2[s] = nb;
    } else {
        // ---- sort pred bars by persistence descending (reuse mkey) ----
        const int P2 = (nb <= 1024) ? 1024 : ((nb <= 2048) ? 2048 : 4096);
        for (int i = tid; i < P2; i += NTHR) {
            if (i < nb) {
                float p = barB[i] - barD[i];
                mkey[i] = (((unsigned long long)(~ford(p))) << 32) | (unsigned)i;
            } else {
                mkey[i] = ~0ull;
            }
        }
        __syncthreads();
        bitonic_sort(mkey, P2, tid);

        for (int i = tid; i < nb; i += NTHR) {
            int idx = (int)(mkey[i] & 0xFFFFFFFFu);
            g_bb[s][i] = barB[idx];
            g_bd[s][i] = barD[idx];
        }
        if (tid == 0) g_k1[s] = nb;
    }

    // ---- fused loss: the last block to finish computes the final scalar ----
    __threadfence();
    __syncthreads();
    if (tid == 0) {
        int old = atomicAdd(&g_done, 1);
        ctrl[5] = (old == 7) ? 1 : 0;
    }
    __syncthreads();
    if (!ctrl[5]) return;
    __threadfence();

    float* red = (float*)best;   // free scratch now
    float acc = 0.f;
    for (int ss = 0; ss < 4; ++ss) {
        const int K1 = g_k1[ss], K2 = g_k2[ss];
        const int m  = min(K1, K2);
        for (int t = tid; t < K1; t += NTHR) {
            float b = g_bb[ss][t], d = g_bd[ss][t];
            if (t < m) {
                float db = b - 1.0f;
                acc += db * db + d * d;
            } else {
                float q = b - d;
                acc += 0.5f * q * q;
            }
        }
        if (tid == 0 && K2 > K1)
            acc += 0.5f * (float)(K2 - K1);
    }
    red[tid] = acc;
    __syncthreads();
    for (int off = 512; off > 0; off >>= 1) {
        if (tid < off) red[tid] += red[tid + off];
        __syncthreads();
    }
    if (tid == 0) {
        out[0] = red[0] * 0.25f;
        g_done = 0;   // reset for next graph replay
    }
}

extern "C" void kernel_launch(void* const* d_in, const int* in_sizes, int n_in,
                              void* d_out, int out_size)
{
    (void)in_sizes; (void)n_in; (void)out_size;
    const float* input  = (const float*)d_in[0];   // (4,2,64,64) float32
    const float* target = (const float*)d_in[1];   // (4,64,64)   float32

    cudaFuncSetAttribute(diagram_kernel,
                         cudaFuncAttributeMaxDynamicSharedMemorySize, SMEM_BYTES);
    diagram_kernel<<<8, NTHR, SMEM_BYTES>>>(input, target, (float*)d_out);
}

// round 5
// speedup vs baseline: 16.1714x; 1.3200x over previous
#include <cuda_runtime.h>
#include <math.h>
#include <stdint.h>

#define HW    64
#define NPIX  4096
#define NEDGE 8064      // 4032 horizontal + 4032 vertical
#define NTHR  1024
#define FULLM 0xFFFFFFFFu

__device__ float g_bb[4][NPIX];
__device__ float g_bd[4][NPIX];
__device__ int   g_k1[4];
__device__ int   g_k2[4];
__device__ int   g_done;        // zero-init; finisher resets to 0 for graph replay

// monotone float<->uint order map
__device__ __forceinline__ unsigned ford(float f) {
    unsigned u = __float_as_uint(f);
    return (u & 0x80000000u) ? ~u : (u | 0x80000000u);
}
__device__ __forceinline__ float iford(unsigned m) {
    unsigned u = (m & 0x80000000u) ? (m ^ 0x80000000u) : ~m;
    return __uint_as_float(u);
}

// Shared layout (dynamic):
//   val  f32[4096]   @0        16384
//   par  i32[4096]   @16384    16384
//   best u64[4096]   @32768    32768   (also loss-reduction scratch)
//   mkey u64[4096]   @65536    32768   (MST edge keys; reused for persistence sort)
//   barB f32[4096]   @98304    16384   (alias: int tmp[4096] hook targets)
//   barD f32[4096]   @114688   16384   (alias: u16 plist[4096] peaks list)
//   used u32[252]    @131072    1008
//   ctrl i32[16]     @132096      64
//   hk   u64[4096]   @132160   32768
//   peak i32[4096]   @164928   16384
//   eA   u16[8064]   @181312   16128
//   eB   u16[8064]   @197440   16128   -> 213568 total
#define SMEM_BYTES 213568
// ctrl: [0]=mstCnt [2]=minbits [3]=nbars [4]=flag [5]=finish [6]=maxbits [7]=npk [8],[9]=edge counters

extern __shared__ unsigned char smem_raw[];

__device__ __forceinline__ void bitonic_sort(unsigned long long* key, int P, int tid) {
    for (int k = 2; k <= P; k <<= 1) {
        for (int j = k >> 1; j > 0; j >>= 1) {
            for (int i = tid; i < P; i += NTHR) {
                int l = i ^ j;
                if (l > i) {
                    bool up = ((i & k) == 0);
                    unsigned long long a = key[i], b = key[l];
                    if ((a > b) == up) { key[i] = b; key[l] = a; }
                }
            }
            __syncthreads();
        }
    }
}

__device__ __forceinline__ void edge_decode(int e, int& u, int& v) {
    if (e < 4032) { int r = e / 63, c = e - r * 63; u = r * 64 + c; v = u + 1; }
    else          { u = e - 4032; v = u + 64; }
}

__global__ void __launch_bounds__(1024)
diagram_kernel(const float* __restrict__ input, const float* __restrict__ target,
               float* __restrict__ out)
{
    const int s    = blockIdx.x & 3;
    const int kind = blockIdx.x >> 2;
    const int tid  = threadIdx.x;

    float* val = (float*)smem_raw;
    int*   par = (int*)(smem_raw + 16384);
    unsigned long long* best = (unsigned long long*)(smem_raw + 32768);
    unsigned long long* mkey = (unsigned long long*)(smem_raw + 65536);
    float* barB = (float*)(smem_raw + 98304);
    int*   tmp  = (int*)  (smem_raw + 98304);
    float* barD = (float*)(smem_raw + 114688);
    unsigned short* plist = (unsigned short*)(smem_raw + 114688);
    unsigned* used = (unsigned*)(smem_raw + 131072);
    int* ctrl = (int*)(smem_raw + 132096);
    unsigned* uctrl = (unsigned*)ctrl;
    unsigned long long* hk = (unsigned long long*)(smem_raw + 132160);
    int* peak = (int*)(smem_raw + 164928);
    unsigned short* eA = (unsigned short*)(smem_raw + 181312);
    unsigned short* eB = (unsigned short*)(smem_raw + 197440);

    if (tid == 0) {
        ctrl[0] = 0; ctrl[3] = 0; ctrl[4] = 0; uctrl[2] = FULLM; uctrl[6] = 0u;
        ctrl[7] = 0; ctrl[8] = 0; ctrl[9] = 0;
    }
    for (int i = tid; i < 252; i += NTHR) used[i] = 0u;
    __syncthreads();

    // ---- fill ----
    #pragma unroll
    for (int rep = 0; rep < 4; ++rep) {
        int i = tid + rep * NTHR;
        float v;
        if (kind == 0) {
            float l0 = input[(s * 2 + 0) * NPIX + i];
            float l1 = input[(s * 2 + 1) * NPIX + i];
            v = 1.0f / (1.0f + expf(l0 - l1));   // == softmax fg channel
        } else {
            v = target[s * NPIX + i];
        }
        val[i] = v;
        hk[i]  = (((unsigned long long)ford(v)) << 12) | (unsigned)(4095 - i);
        mkey[i] = ~0ull;
        unsigned fb = ford(v);
        unsigned wmin = __reduce_min_sync(FULLM, fb);
        unsigned wmax = __reduce_max_sync(FULLM, fb);
        if ((tid & 31) == 0) { atomicMin(&uctrl[2], wmin); atomicMax(&uctrl[6], wmax); }
    }
    __syncthreads();
    const float minv = iford(uctrl[2]);
    const float maxv = iford(uctrl[6]);

    if (kind == 1) {
        // ======== fast path: binary target -> #components of {val > min} ========
        #pragma unroll
        for (int rep = 0; rep < 4; ++rep) {
            int i = tid + rep * NTHR;
            par[i] = (val[i] > minv) ? i : 0x7FFFFFFF;
        }
        __syncthreads();
        for (int it = 0; it < 64; ++it) {
            int chg = 0;
            #pragma unroll
            for (int rep = 0; rep < 4; ++rep) {
                int i = tid + rep * NTHR;
                int m = par[i];
                if (m != 0x7FFFFFFF) {
                    int r = i >> 6, c = i & 63;
                    if (r > 0)  { int q = par[i - 64]; if (q < m) m = q; }
                    if (r < 63) { int q = par[i + 64]; if (q < m) m = q; }
                    if (c > 0)  { int q = par[i - 1];  if (q < m) m = q; }
                    if (c < 63) { int q = par[i + 1];  if (q < m) m = q; }
                    m = par[m];                  // jump
                    if (m < par[i]) { par[i] = m; chg = 1; }
                }
            }
            if (chg) ctrl[4] = 1;
            __syncthreads();
            int c4 = ctrl[4];
            __syncthreads();
            if (tid == 0) ctrl[4] = 0;
            if (!c4) break;
            __syncthreads();
        }
        int cnt = 0;
        #pragma unroll
        for (int rep = 0; rep < 4; ++rep) {
            int i = tid + rep * NTHR;
            if (par[i] == i) cnt++;
        }
        cnt = __reduce_add_sync(FULLM, cnt);
        if ((tid & 31) == 0) atomicAdd(&ctrl[3], cnt);
        __syncthreads();
        if (tid == 0) g_k2[s] = ctrl[3];
    } else {
        // ======== pred path: full persistence pipeline ========
        // steepest strictly-higher neighbor hook -> peak labels
        #pragma unroll
        for (int rep = 0; rep < 4; ++rep) {
            int i = tid + rep * NTHR;
            unsigned long long h = hk[i];
            int r = i >> 6, c = i & 63;
            int p = i;
            if      (r < 63 && hk[i + 64] > h) p = i + 64;
            else if (r > 0  && hk[i - 64] > h) p = i - 64;
            else if (c < 63 && hk[i + 1]  > h) p = i + 1;
            else if (c > 0  && hk[i - 1]  > h) p = i - 1;
            par[i] = p;
        }
        __syncthreads();
        for (int it = 0; it < 12; ++it) {       // pointer doubling w/ convergence
            int chg = 0;
            #pragma unroll
            for (int rep = 0; rep < 4; ++rep) {
                int i = tid + rep * NTHR;
                int p = par[i]; int pp = par[p];
                if (p != pp) { par[i] = pp; chg = 1; }
            }
            if (chg) ctrl[4] = 1;
            __syncthreads();
            int c4 = ctrl[4];
            __syncthreads();
            if (tid == 0) ctrl[4] = 0;
            if (!c4) break;
            __syncthreads();
        }
        #pragma unroll
        for (int rep = 0; rep < 4; ++rep) {
            int i = tid + rep * NTHR;
            int p = par[i];
            peak[i] = p;
            if (p == i) { int slot = atomicAdd(&ctrl[7], 1); plist[slot] = (unsigned short)i; }
        }
        __syncthreads();
        const int npk = ctrl[7];

        // ---- Boruvka over regions with compacted edge lists ----
        int Ecur = NEDGE;
        for (int round = 0; Ecur > 0 && round < 20; ++round) {
            if (tid == 0) ctrl[8 + ((round + 1) & 1)] = 0;
            for (int t = tid; t < npk; t += NTHR) best[plist[t]] = 0ull;
            __syncthreads();

            const unsigned short* src = (round & 1) ? eB : eA;
            unsigned short*       dst = (round & 1) ? eA : eB;
            int* nxt = &ctrl[8 + ((round + 1) & 1)];
            for (int idx = tid; idx < Ecur; idx += NTHR) {
                int e = (round == 0) ? idx : (int)src[idx];
                int u, v; edge_decode(e, u, v);
                int ru = par[peak[u]], rv = par[peak[v]];
                if (ru == rv) continue;
                int slot = atomicAdd(nxt, 1);
                dst[slot] = (unsigned short)e;
                unsigned long long hu = hk[u], hv = hk[v];
                unsigned long long low = hu < hv ? hu : hv;
                unsigned long long sc = (low << 13) | (unsigned)e;
                atomicMax(&best[ru], sc);
                atomicMax(&best[rv], sc);
            }
            __syncthreads();
            int Enext = ctrl[8 + ((round + 1) & 1)];
            if (Enext == 0) break;

            // record MST edges (dedup) + stage hook targets (frozen par)
            for (int t = tid; t < npk; t += NTHR) {
                int r = plist[t];
                if (par[r] == r) {
                    unsigned long long sc = best[r];
                    if (sc) {
                        int e = (int)(sc & 0x1FFF);
                        int u, v; edge_decode(e, u, v);
                        int ru = par[peak[u]], rv = par[peak[v]];
                        tmp[r] = (ru == r) ? rv : ru;
                        int w = e >> 5; unsigned b = 1u << (e & 31);
                        if (!(atomicOr(&used[w], b) & b)) {
                            int slot = atomicAdd(&ctrl[0], 1);
                            mkey[slot] = ~sc;
                        }
                    }
                }
            }
            __syncthreads();
            // hook
            for (int t = tid; t < npk; t += NTHR) {
                int r = plist[t];
                if (par[r] == r && best[r]) par[r] = tmp[r];
            }
            __syncthreads();
            // break mutual 2-cycles (smaller index stays root)
            for (int t = tid; t < npk; t += NTHR) {
                int r = plist[t];
                int p = par[r];
                if (p != r && par[p] == r && r < p) par[r] = r;
            }
            __syncthreads();
            // flatten peak entries (all chain nodes are peaks)
            for (int it = 0; it < 13; ++it) {
                int chg = 0;
                for (int t = tid; t < npk; t += NTHR) {
                    int p = plist[t];
                    int a = par[p]; int b = par[a];
                    if (a != b) { par[p] = b; chg = 1; }
                }
                if (chg) ctrl[4] = 1;
                __syncthreads();
                int c4 = ctrl[4];
                __syncthreads();
                if (tid == 0) ctrl[4] = 0;
                if (!c4) break;
                __syncthreads();
            }
            Ecur = Enext;
        }
        __syncthreads();
        const int nmst = min(ctrl[0], NPIX);

        // ---- sort MST edges: ~score ascending == Kruskal order ----
        const int P = (nmst <= 1024) ? 1024 : ((nmst <= 2048) ? 2048 : 4096);
        bitonic_sort(mkey, P, tid);

        // reseed pairing UF over peaks
        for (int t = tid; t < npk; t += NTHR) { int p = plist[t]; par[p] = p; }
        __syncthreads();

        // ---- warp-speculative Kruskal pairing (warp 0) ----
        if (tid < 32) {
            for (int base = 0; base < nmst; base += 32) {
                int t = base + tid;
                bool has = t < nmst;
                int dIdx = 0, ru = 0, rv = 0;
                unsigned long long hu = 0, hv = 0;
                if (has) {
                    unsigned long long sc = ~mkey[t];
                    int e = (int)(sc & 0x1FFF);
                    int uu, vv; edge_decode(e, uu, vv);
                    dIdx = 4095 - (int)((sc >> 13) & 0xFFF);
                    ru = peak[uu];
                    for (;;) { int p = par[ru]; if (p == ru) break; int gp = par[p]; par[ru] = gp; ru = gp; }
                    rv = peak[vv];
                    for (;;) { int p = par[rv]; if (p == rv) break; int gp = par[p]; par[rv] = gp; rv = gp; }
                    hu = hk[ru]; hv = hk[rv];
                }
                __syncwarp(FULLM);
                int young = -1, elder = -1;
                #pragma unroll 4
                for (int k = 0; k < 32; ++k) {
                    unsigned pk = 0xFFFFFFFFu;
                    if (tid == k && has && ru != rv) {
                        if (hu > hv) { elder = ru; young = rv; }
                        else         { elder = rv; young = ru; }
                        pk = ((unsigned)young << 16) | (unsigned)elder;
                    }
                    pk = __shfl_sync(FULLM, pk, k);
                    if (pk != 0xFFFFFFFFu && tid > k) {
                        int yk = (int)(pk >> 16), ek = (int)(pk & 0xFFFFu);
                        if (ru == yk) { ru = ek; hu = hk[ek]; }
                        if (rv == yk) { rv = ek; hv = hk[ek]; }
                    }
                }
                if (young >= 0) {
                    par[young] = elder;
                    float bv = val[young];
                    float dv = val[dIdx];
                    if (bv > dv) {
                        int slot = atomicAdd(&ctrl[3], 1);
                        barB[slot] = bv; barD[slot] = dv;
                    }
                }
                __syncwarp(FULLM);
            }
        }
        __syncthreads();

        // essential bar: single surviving root = global max pixel
        if (tid == 0 && maxv > minv) {
            int slot = atomicAdd(&ctrl[3], 1);
            barB[slot] = maxv; barD[slot] = minv;
        }
        __syncthreads();
        const int nb = ctrl[3];

        // ---- sort pred bars by persistence descending ----
        const int P2 = (nb <= 1024) ? 1024 : ((nb <= 2048) ? 2048 : 4096);
        for (int i = tid; i < P2; i += NTHR) {
            if (i < nb) {
                float p = barB[i] - barD[i];
                mkey[i] = (((unsigned long long)(~ford(p))) << 32) | (unsigned)i;
            } else {
                mkey[i] = ~0ull;
            }
        }
        __syncthreads();
        bitonic_sort(mkey, P2, tid);

        for (int i = tid; i < nb; i += NTHR) {
            int idx = (int)(mkey[i] & 0xFFFFFFFFu);
            g_bb[s][i] = barB[idx];
            g_bd[s][i] = barD[idx];
        }
        if (tid == 0) g_k1[s] = nb;
    }

    // ---- fused loss: last block to finish computes the final scalar ----
    __threadfence();
    __syncthreads();
    if (tid == 0) {
        int old = atomicAdd(&g_done, 1);
        ctrl[5] = (old == 7) ? 1 : 0;
    }
    __syncthreads();
    if (!ctrl[5]) return;
    __threadfence();

    float* red = (float*)best;
    float acc = 0.f;
    for (int ss = 0; ss < 4; ++ss) {
        const int K1 = g_k1[ss], K2 = g_k2[ss];
        const int m  = min(K1, K2);
        for (int t = tid; t < K1; t += NTHR) {
            float b = g_bb[ss][t], d = g_bd[ss][t];
            if (t < m) {
                float db = b - 1.0f;
                acc += db * db + d * d;
            } else {
                float q = b - d;
                acc += 0.5f * q * q;
            }
        }
        if (tid == 0 && K2 > K1)
            acc += 0.5f * (float)(K2 - K1);
    }
    red[tid] = acc;
    __syncthreads();
    for (int off = 512; off > 0; off >>= 1) {
        if (tid < off) red[tid] += red[tid + off];
        __syncthreads();
    }
    if (tid == 0) {
        out[0] = red[0] * 0.25f;
        g_done = 0;
    }
}

extern "C" void kernel_launch(void* const* d_in, const int* in_sizes, int n_in,
                              void* d_out, int out_size)
{
    (void)in_sizes; (void)n_in; (void)out_size;
    const float* input  = (const float*)d_in[0];   // (4,2,64,64) float32
    const float* target = (const float*)d_in[1];   // (4,64,64)   float32

    cudaFuncSetAttribute(diagram_kernel,
                         cudaFuncAttributeMaxDynamicSharedMemorySize, SMEM_BYTES);
    diagram_kernel<<<8, NTHR, SMEM_BYTES>>>(input, target, (float*)d_out);
}